// round 2
// baseline (speedup 1.0000x reference)
#include <cuda_runtime.h>
#include <cuda_bf16.h>

// LocalEqFeatureExtraction: per-voxel pointnet-ish feature extraction.
// x[v,p,:] = [coords(3), pt_feat(1), coords-mean(3) (masked by p<npts),
//             dist(p,q)*(q<npts) for q=0..19]        (27 channels)
// out[v,o] = max_p relu( (x[v,p,:] @ W[:,o] - rm[o]) * rsqrt(rv[o]+eps)*g[o] + b[o] )

#define VPB 8          // voxels per block
#define NTHR 64        // one thread per output channel
#define P 20
#define CIN 27
#define CPAD 28        // padded row width (float4-aligned stride, col 27 == 0)

__global__ __launch_bounds__(NTHR) void lef_kernel(
    const float* __restrict__ feats,      // V*20*4
    const int*   __restrict__ num_points, // V
    const float* __restrict__ W,          // 27*64 row-major [c][o]
    const float* __restrict__ gamma_,     // 64
    const float* __restrict__ beta_,      // 64
    const float* __restrict__ rmean,      // 64
    const float* __restrict__ rvar,       // 64
    float* __restrict__ out,              // V*64
    int V)
{
    __shared__ alignas(16) float xs[P][CPAD];  // assembled input rows (16B aligned!)
    __shared__ float cs[P][3];     // coords
    __shared__ float fs[P];        // pt feature (channel 3)
    __shared__ float sq[P];        // |coords|^2
    __shared__ float mean3[3];

    const int o = threadIdx.x;     // output channel 0..63

    // W column into registers (reused across VPB voxels)
    float Wreg[CPAD];
    #pragma unroll
    for (int c = 0; c < CIN; ++c) Wreg[c] = W[c * 64 + o];
    Wreg[27] = 0.0f;

    // fold BN affine
    const float scale = gamma_[o] * rsqrtf(rvar[o] + 1e-3f);
    const float shift = beta_[o] - rmean[o] * scale;

    const int v0 = blockIdx.x * VPB;

    for (int vi = 0; vi < VPB; ++vi) {
        const int v = v0 + vi;
        if (v >= V) break;                      // uniform across block

        const int npts = num_points[v];

        // ---- stage features (80 consecutive floats, coalesced) ----
        const float* f = feats + (size_t)v * (P * 4);
        for (int i = o; i < P * 4; i += NTHR) {
            float val = f[i];
            int p = i >> 2, c = i & 3;
            if (c < 3) cs[p][c] = val; else fs[p] = val;
        }
        __syncthreads();

        // ---- sq[p] and unmasked mean (matches reference: sum all P / npts) ----
        if (o < P)
            sq[o] = cs[o][0]*cs[o][0] + cs[o][1]*cs[o][1] + cs[o][2]*cs[o][2];
        if (o < 3) {
            float s = 0.0f;
            #pragma unroll
            for (int p = 0; p < P; ++p) s += cs[p][o];
            mean3[o] = s / (float)npts;
        }
        __syncthreads();

        // ---- assemble x rows (reference's expansion distance formula) ----
        for (int idx = o; idx < P * CPAD; idx += NTHR) {
            const int p = idx / CPAD, c = idx % CPAD;
            float val = 0.0f;
            if (c < 7) {
                float nv;
                if (c < 3)       nv = cs[p][c];
                else if (c == 3) nv = fs[p];
                else             nv = cs[p][c - 4] - mean3[c - 4];
                val = (p < npts) ? nv : 0.0f;
            } else if (c < CIN) {
                const int q = c - 7;
                if (q < npts) {
                    float dot = cs[p][0] * cs[q][0];
                    dot = fmaf(cs[p][1], cs[q][1], dot);
                    dot = fmaf(cs[p][2], cs[q][2], dot);
                    float d2 = (sq[p] + sq[q]) - 2.0f * dot;
                    val = (d2 > 0.0f) ? sqrtf(d2) : 0.0f;
                }
            }
            xs[p][c] = val;
        }
        __syncthreads();

        // ---- per-channel GEMV + BN + relu + max over p ----
        float best = 0.0f;   // relu(v) >= 0, so max starts at 0
        #pragma unroll 5
        for (int p = 0; p < P; ++p) {
            const float4* row = (const float4*)xs[p];  // broadcast LDS.128
            float d0 = 0.0f, d1 = 0.0f;
            #pragma unroll
            for (int j = 0; j < 7; j += 2) {           // j = 0,2,4,6
                float4 t = row[j];
                d0 = fmaf(t.x, Wreg[4*j+0], d0);
                d0 = fmaf(t.y, Wreg[4*j+1], d0);
                d0 = fmaf(t.z, Wreg[4*j+2], d0);
                d0 = fmaf(t.w, Wreg[4*j+3], d0);
                if (j + 1 < 7) {
                    float4 u = row[j+1];
                    d1 = fmaf(u.x, Wreg[4*j+4], d1);
                    d1 = fmaf(u.y, Wreg[4*j+5], d1);
                    d1 = fmaf(u.z, Wreg[4*j+6], d1);
                    d1 = fmaf(u.w, Wreg[4*j+7], d1);
                }
            }
            float val = fmaf(d0 + d1, scale, shift);
            best = fmaxf(best, val);
        }
        out[(size_t)v * 64 + o] = best;
        __syncthreads();   // protect smem before next voxel
    }
}

extern "C" void kernel_launch(void* const* d_in, const int* in_sizes, int n_in,
                              void* d_out, int out_size) {
    const float* feats      = (const float*)d_in[0];
    const int*   num_points = (const int*)  d_in[1];
    // d_in[2] = coors (unused by reference)
    const float* W          = (const float*)d_in[3];
    const float* gamma_     = (const float*)d_in[4];
    const float* beta_      = (const float*)d_in[5];
    const float* rmean      = (const float*)d_in[6];
    const float* rvar       = (const float*)d_in[7];
    float* out = (float*)d_out;

    const int V = in_sizes[1];                 // num_points has V elements
    const int grid = (V + VPB - 1) / VPB;
    lef_kernel<<<grid, NTHR>>>(feats, num_points, W, gamma_, beta_, rmean, rvar, out, V);
}

// round 3
// speedup vs baseline: 1.7533x; 1.7533x over previous
#include <cuda_runtime.h>
#include <cuda_bf16.h>

// LocalEqFeatureExtraction, warp-per-voxel-stream, f32x2-packed GEMV.
// out[v,o] = max_p relu( (x[v,p,:] @ W[:,o]) * scale_o + shift_o )
// x[p] = [coords(3), feat(1), coords-mean(3)] * (p<npts)  ++  dist(p,q)*(q<npts)
// Node part computed analytically: mask_p * ( c0*(W0+W4)+c1*(W1+W5)+c2*(W2+W6)+f*W3 - m.W[4:7] )

typedef unsigned long long u64;

__device__ __forceinline__ u64 ffma2(u64 a, u64 b, u64 c) {
    u64 d; asm("fma.rn.f32x2 %0,%1,%2,%3;" : "=l"(d) : "l"(a), "l"(b), "l"(c)); return d;
}
__device__ __forceinline__ u64 fadd2(u64 a, u64 b) {
    u64 d; asm("add.rn.f32x2 %0,%1,%2;" : "=l"(d) : "l"(a), "l"(b)); return d;
}
__device__ __forceinline__ u64 pack2(float lo, float hi) {
    u64 d; asm("mov.b64 %0,{%1,%2};" : "=l"(d) : "f"(lo), "f"(hi)); return d;
}
__device__ __forceinline__ float hadd2(u64 a) {
    float lo, hi; asm("mov.b64 {%0,%1},%2;" : "=f"(lo), "=f"(hi) : "l"(a)); return lo + hi;
}
__device__ __forceinline__ float sqrt_approx(float x) {
    float r; asm("sqrt.approx.f32 %0,%1;" : "=f"(r) : "f"(x)); return r;
}

#define P 20
#define NWARP 4     // warps per block, each warp independent
#define VPW 4       // voxels per warp

struct alignas(16) WarpSmem {
    float4 cs4[P];      // raw (c0,c1,c2,feat)           320 B
    float  sq[P];       // |coords|^2                     80 B
    float  es[P][P];    // dist(p,q)*(q<npts)           1600 B  (row stride 80B, 16B aligned)
};

__global__ void __launch_bounds__(NWARP * 32) lef_kernel(
    const float4* __restrict__ feats4,    // V*20 float4
    const int*    __restrict__ num_points,
    const float*  __restrict__ W,         // 27 x 64, row-major [c][o]
    const float*  __restrict__ gamma_,
    const float*  __restrict__ beta_,
    const float*  __restrict__ rmean,
    const float*  __restrict__ rvar,
    float* __restrict__ out,              // V x 64
    int V)
{
    __shared__ WarpSmem ws_all[NWARP];
    const int lane = threadIdx.x & 31;
    const int warp = threadIdx.x >> 5;
    WarpSmem& ws = ws_all[warp];

    const int o0 = lane, o1 = lane + 32;   // this thread's two output channels

    // ---- per-thread weights (held across all voxels) ----
    // node combined: A01 = (W0+W4, W1+W5), A23 = (W2+W6, W3)
    const u64 A01a = pack2(W[0*64+o0] + W[4*64+o0], W[1*64+o0] + W[5*64+o0]);
    const u64 A23a = pack2(W[2*64+o0] + W[6*64+o0], W[3*64+o0]);
    const u64 A01b = pack2(W[0*64+o1] + W[4*64+o1], W[1*64+o1] + W[5*64+o1]);
    const u64 A23b = pack2(W[2*64+o1] + W[6*64+o1], W[3*64+o1]);
    const float w4a = W[4*64+o0], w5a = W[5*64+o0], w6a = W[6*64+o0];
    const float w4b = W[4*64+o1], w5b = W[5*64+o1], w6b = W[6*64+o1];

    u64 weA[10], weB[10];                 // edge weights, packed pairs
    #pragma unroll
    for (int k = 0; k < 10; ++k) {
        weA[k] = pack2(W[(7 + 2*k)*64 + o0], W[(8 + 2*k)*64 + o0]);
        weB[k] = pack2(W[(7 + 2*k)*64 + o1], W[(8 + 2*k)*64 + o1]);
    }

    const float scale0 = gamma_[o0] * rsqrtf(rvar[o0] + 1e-3f);
    const float shift0 = beta_[o0] - rmean[o0] * scale0;
    const float scale1 = gamma_[o1] * rsqrtf(rvar[o1] + 1e-3f);
    const float shift1 = beta_[o1] - rmean[o1] * scale1;

    const u64 zero2 = 0;

    const int vbase = (blockIdx.x * NWARP + warp) * VPW;

    #pragma unroll 1
    for (int vi = 0; vi < VPW; ++vi) {
        const int v = vbase + vi;
        if (v >= V) break;                    // warp-uniform
        const int npts = num_points[v];

        // ---- stage point data (one LDG.128 per lane 0..19) ----
        float4 t = make_float4(0.f, 0.f, 0.f, 0.f);
        if (lane < P) {
            t = feats4[(size_t)v * P + lane];
            ws.cs4[lane] = t;
            ws.sq[lane]  = t.x*t.x + t.y*t.y + t.z*t.z;
        }
        // mean of raw coords over ALL P points, / npts (matches reference)
        float mx = t.x, my = t.y, mz = t.z;
        #pragma unroll
        for (int off = 16; off; off >>= 1) {
            mx += __shfl_xor_sync(0xffffffffu, mx, off);
            my += __shfl_xor_sync(0xffffffffu, my, off);
            mz += __shfl_xor_sync(0xffffffffu, mz, off);
        }
        const float nf = (float)npts;
        const float m0 = mx / nf, m1 = my / nf, m2 = mz / nf;
        __syncwarp();

        // ---- distance matrix: es[p][q] = (q<npts && d2>0) ? sqrt(d2) : 0 ----
        #pragma unroll 1
        for (int idx = lane; idx < P * P; idx += 32) {
            const int p = idx / P;            // magic-mul division
            const int q = idx - p * P;
            const float4 a = ws.cs4[p];
            const float4 b = ws.cs4[q];
            float dot = a.x * b.x;
            dot = fmaf(a.y, b.y, dot);
            dot = fmaf(a.z, b.z, dot);
            const float d2 = (ws.sq[p] + ws.sq[q]) - 2.0f * dot;
            float val = 0.0f;
            if (d2 > 0.0f && q < npts) val = sqrt_approx(d2);
            ws.es[p][q] = val;
        }
        __syncwarp();

        // per-voxel node constants
        const float mWa = fmaf(m0, w4a, fmaf(m1, w5a, m2 * w6a));
        const float mWb = fmaf(m0, w4b, fmaf(m1, w5b, m2 * w6b));

        // ---- GEMV + BN + relu + max over p (fully unrolled) ----
        float best0 = 0.0f, best1 = 0.0f;     // relu >= 0
        #pragma unroll
        for (int p = 0; p < P; ++p) {
            const ulonglong2* nr2 = (const ulonglong2*)&ws.cs4[p];
            const ulonglong2  nr  = *nr2;                 // (c0,c1) , (c2,f)
            const ulonglong2* er  = (const ulonglong2*)ws.es[p];
            const ulonglong2 e0 = er[0], e1 = er[1], e2 = er[2], e3 = er[3], e4 = er[4];
            const float pm = (p < npts) ? 1.0f : 0.0f;

            // channel 0: edge dot (dual accumulators)
            u64 s0 = ffma2(e0.x, weA[0], zero2);
            u64 s1 = ffma2(e0.y, weA[1], zero2);
            s0 = ffma2(e1.x, weA[2], s0);
            s1 = ffma2(e1.y, weA[3], s1);
            s0 = ffma2(e2.x, weA[4], s0);
            s1 = ffma2(e2.y, weA[5], s1);
            s0 = ffma2(e3.x, weA[6], s0);
            s1 = ffma2(e3.y, weA[7], s1);
            s0 = ffma2(e4.x, weA[8], s0);
            s1 = ffma2(e4.y, weA[9], s1);
            const float edge0 = hadd2(fadd2(s0, s1));
            const u64 na = ffma2(nr.x, A01a, ffma2(nr.y, A23a, zero2));
            const float node0 = (hadd2(na) - mWa) * pm;
            const float tot0  = node0 + edge0;
            best0 = fmaxf(best0, fmaf(tot0, scale0, shift0));

            // channel 1
            u64 r0 = ffma2(e0.x, weB[0], zero2);
            u64 r1 = ffma2(e0.y, weB[1], zero2);
            r0 = ffma2(e1.x, weB[2], r0);
            r1 = ffma2(e1.y, weB[3], r1);
            r0 = ffma2(e2.x, weB[4], r0);
            r1 = ffma2(e2.y, weB[5], r1);
            r0 = ffma2(e3.x, weB[6], r0);
            r1 = ffma2(e3.y, weB[7], r1);
            r0 = ffma2(e4.x, weB[8], r0);
            r1 = ffma2(e4.y, weB[9], r1);
            const float edge1 = hadd2(fadd2(r0, r1));
            const u64 nb = ffma2(nr.x, A01b, ffma2(nr.y, A23b, zero2));
            const float node1 = (hadd2(nb) - mWb) * pm;
            const float tot1  = node1 + edge1;
            best1 = fmaxf(best1, fmaf(tot1, scale1, shift1));
        }

        out[(size_t)v * 64 + o0] = best0;
        out[(size_t)v * 64 + o1] = best1;
        __syncwarp();   // protect smem before next voxel's staging
    }
}

extern "C" void kernel_launch(void* const* d_in, const int* in_sizes, int n_in,
                              void* d_out, int out_size) {
    const float4* feats4     = (const float4*)d_in[0];
    const int*    num_points = (const int*)   d_in[1];
    // d_in[2] = coors (unused by reference)
    const float*  W          = (const float*) d_in[3];
    const float*  gamma_     = (const float*) d_in[4];
    const float*  beta_      = (const float*) d_in[5];
    const float*  rmean      = (const float*) d_in[6];
    const float*  rvar       = (const float*) d_in[7];
    float* out = (float*)d_out;

    const int V = in_sizes[1];
    const int vox_per_block = NWARP * VPW;
    const int grid = (V + vox_per_block - 1) / vox_per_block;
    lef_kernel<<<grid, NWARP * 32>>>(feats4, num_points, W, gamma_, beta_, rmean, rvar, out, V);
}

// round 5
// speedup vs baseline: 2.1046x; 1.2004x over previous
#include <cuda_runtime.h>
#include <cuda_bf16.h>
#include <stdint.h>

#define PP 20
#define VPW 4          // voxels per warp
#define WARPS 2
#define THREADS 64
#define ROWS_W 80      // A rows per warp
#define ASTR 80        // bytes per A row (32 bf16 = 64B data + 16B pad)

__device__ __forceinline__ uint32_t smem_u32(const void* p) {
    uint32_t a;
    asm("{ .reg .u64 t; cvta.to.shared.u64 t, %1; cvt.u32.u64 %0, t; }" : "=r"(a) : "l"(p));
    return a;
}
__device__ __forceinline__ float sqrt_apx(float x) {
    float r; asm("sqrt.approx.f32 %0,%1;" : "=f"(r) : "f"(x)); return r;
}
__device__ __forceinline__ uint32_t pack_bf2(float x, float y) {
    __nv_bfloat162 t = __floats2bfloat162_rn(x, y);
    return *(uint32_t*)&t;
}
__device__ __forceinline__ uint32_t pack_res2(float x, float y, uint32_t hipack) {
    __nv_bfloat162 h = *(__nv_bfloat162*)&hipack;
    return pack_bf2(x - __bfloat162float(h.x), y - __bfloat162float(h.y));
}
// monotone float -> uint key (order-preserving for all floats)
__device__ __forceinline__ uint32_t fkey(float f) {
    int s = __float_as_int(f);
    return (uint32_t)(s ^ ((s >> 31) | 0x80000000));
}
__device__ __forceinline__ float funkey(uint32_t u) {
    int s = (u & 0x80000000u) ? (int)(u ^ 0x80000000u) : ~(int)u;
    return __int_as_float(s);
}
__device__ __forceinline__ void ldmat4(uint32_t* r, uint32_t addr) {
    asm volatile("ldmatrix.sync.aligned.m8n8.x4.shared.b16 {%0,%1,%2,%3}, [%4];"
        : "=r"(r[0]), "=r"(r[1]), "=r"(r[2]), "=r"(r[3]) : "r"(addr));
}
__device__ __forceinline__ void mma16816(float* c, const uint32_t* a, const uint32_t* b) {
    asm volatile("mma.sync.aligned.m16n8k16.row.col.f32.bf16.bf16.f32 "
        "{%0,%1,%2,%3},{%4,%5,%6,%7},{%8,%9},{%0,%1,%2,%3};"
        : "+f"(c[0]), "+f"(c[1]), "+f"(c[2]), "+f"(c[3])
        : "r"(a[0]), "r"(a[1]), "r"(a[2]), "r"(a[3]), "r"(b[0]), "r"(b[1]));
}
// permuted W lookup: k<20 -> dist weight row 7+k ; 20..26 -> node row k-20 ; else 0
__device__ __forceinline__ float wval(const float* __restrict__ W, int k, int n) {
    if (k < 20) return W[(7 + k) * 64 + n];
    if (k < 27) return W[(k - 20) * 64 + n];
    return 0.0f;
}

__global__ void __launch_bounds__(THREADS) lef_mma_kernel(
    const float4* __restrict__ feats4,
    const int*    __restrict__ num_points,
    const float*  __restrict__ W,
    const float*  __restrict__ gamma_,
    const float*  __restrict__ beta_,
    const float*  __restrict__ rmean,
    const float*  __restrict__ rvar,
    float* __restrict__ out,
    int V)
{
    __shared__ __align__(16) uint8_t Ahi[WARPS][ROWS_W * ASTR];
    __shared__ __align__(16) uint8_t Alo[WARPS][ROWS_W * ASTR];
    __shared__ uint32_t buf[WARPS * VPW][64];
    __shared__ float4  cs4s[WARPS * VPW][PP];
    __shared__ float   sqs [WARPS * VPW][PP];
    __shared__ float   meanv[WARPS * VPW][3];
    __shared__ int     npvs[WARPS * VPW];
    __shared__ float   scls[64], shfs[64];

    const int tid  = threadIdx.x;
    const int warp = tid >> 5;
    const int lane = tid & 31;
    const int t4 = lane & 3, g = lane >> 2;

    // ---- B fragments in registers (hi/lo) ----
    uint32_t Bh[8][2][2], Bl[8][2][2];
    {
        const int n = (0) * 8 + g;  // n depends on nt, computed in loop
        (void)n;
        #pragma unroll
        for (int nt = 0; nt < 8; ++nt) {
            const int nn = nt * 8 + g;
            #pragma unroll
            for (int ks = 0; ks < 2; ++ks) {
                const int k0 = ks * 16 + 2 * t4;
                const float w00 = wval(W, k0,     nn);
                const float w01 = wval(W, k0 + 1, nn);
                const float w10 = wval(W, k0 + 8, nn);
                const float w11 = wval(W, k0 + 9, nn);
                Bh[nt][ks][0] = pack_bf2(w00, w01);
                Bh[nt][ks][1] = pack_bf2(w10, w11);
                Bl[nt][ks][0] = pack_res2(w00, w01, Bh[nt][ks][0]);
                Bl[nt][ks][1] = pack_res2(w10, w11, Bh[nt][ks][1]);
            }
        }
    }

    // ---- init: BN fold, buf zero ----
    {
        const float s = gamma_[tid] * rsqrtf(rvar[tid] + 1e-3f);
        scls[tid] = s;
        shfs[tid] = beta_[tid] - rmean[tid] * s;
        uint32_t* bflat = &buf[0][0];
        #pragma unroll
        for (int i = 0; i < 8; ++i) bflat[tid + i * THREADS] = 0u;
    }

    // ---- stage features per warp ----
    const int v0 = (blockIdx.x * WARPS + warp) * VPW;
    #pragma unroll
    for (int r = lane; r < ROWS_W; r += 32) {
        const int vi = r / PP, p = r - vi * PP;
        const int vv = v0 + vi;
        float4 t = make_float4(0.f, 0.f, 0.f, 0.f);
        if (vv < V) t = feats4[(size_t)vv * PP + p];
        const int sv = warp * VPW + vi;
        cs4s[sv][p] = t;
        sqs[sv][p]  = t.x * t.x + t.y * t.y + t.z * t.z;
    }
    if (lane < VPW) {
        const int vv = v0 + lane;
        npvs[warp * VPW + lane] = (vv < V) ? num_points[vv] : 1;
    }
    __syncthreads();   // buf zero + scl + staging visible

    // ---- per-voxel means ----
    if (lane < 12) {
        const int vi = lane / 3, d = lane - vi * 3;
        const int sv = warp * VPW + vi;
        const float* c = (const float*)&cs4s[sv][0];
        float s = 0.0f;
        #pragma unroll
        for (int p = 0; p < PP; ++p) s += c[p * 4 + d];
        meanv[sv][d] = s / (float)npvs[sv];
    }
    __syncwarp();

    // ---- assemble A rows (hi/lo bf16), 32 bf16 per row ----
    const uint32_t aHiB = smem_u32(&Ahi[warp][0]);
    const uint32_t aLoB = smem_u32(&Alo[warp][0]);
    #pragma unroll
    for (int r = lane; r < ROWS_W; r += 32) {
        const int vi = r / PP, p = r - vi * PP;
        const int sv = warp * VPW + vi;
        const float4 a  = cs4s[sv][p];
        const float sqp = sqs[sv][p];
        const int   np  = npvs[sv];
        const float pm  = (p < np) ? 1.0f : 0.0f;
        const float m0 = meanv[sv][0], m1 = meanv[sv][1], m2 = meanv[sv][2];

        uint32_t hi[16], lo[16];
        #pragma unroll
        for (int jj = 0; jj < 10; ++jj) {
            const int q0 = 2 * jj, q1 = q0 + 1;
            const float4 b0 = cs4s[sv][q0], b1 = cs4s[sv][q1];
            float dot0 = a.x * b0.x; dot0 = fmaf(a.y, b0.y, dot0); dot0 = fmaf(a.z, b0.z, dot0);
            float dot1 = a.x * b1.x; dot1 = fmaf(a.y, b1.y, dot1); dot1 = fmaf(a.z, b1.z, dot1);
            const float d20 = (sqp + sqs[sv][q0]) - 2.0f * dot0;
            const float d21 = (sqp + sqs[sv][q1]) - 2.0f * dot1;
            const float e0 = (d20 > 0.0f && q0 < np) ? sqrt_apx(d20) : 0.0f;
            const float e1 = (d21 > 0.0f && q1 < np) ? sqrt_apx(d21) : 0.0f;
            hi[jj] = pack_bf2(e0, e1);
            lo[jj] = pack_res2(e0, e1, hi[jj]);
        }
        const float n0 = a.x * pm, n1 = a.y * pm, n2 = a.z * pm, n3 = a.w * pm;
        const float n4 = (a.x - m0) * pm, n5 = (a.y - m1) * pm, n6 = (a.z - m2) * pm;
        hi[10] = pack_bf2(n0, n1); lo[10] = pack_res2(n0, n1, hi[10]);
        hi[11] = pack_bf2(n2, n3); lo[11] = pack_res2(n2, n3, hi[11]);
        hi[12] = pack_bf2(n4, n5); lo[12] = pack_res2(n4, n5, hi[12]);
        hi[13] = pack_bf2(n6, 0.f); lo[13] = pack_res2(n6, 0.f, hi[13]);
        hi[14] = hi[15] = lo[14] = lo[15] = 0u;

        uint8_t* rowHi = &Ahi[warp][r * ASTR];
        uint8_t* rowLo = &Alo[warp][r * ASTR];
        const int rot = (lane >> 3) & 3;              // kill STS bank conflicts
        #pragma unroll
        for (int jj = 0; jj < 4; ++jj) {
            const int j = (jj + rot) & 3;
            *(uint4*)(rowHi + j * 16) = make_uint4(hi[4*j], hi[4*j+1], hi[4*j+2], hi[4*j+3]);
            *(uint4*)(rowLo + j * 16) = make_uint4(lo[4*j], lo[4*j+1], lo[4*j+2], lo[4*j+3]);
        }
    }
    __syncwarp();

    // ---- MMA: 5 m-tiles x 8 n-tiles x 2 k-steps x 3 products ----
    #pragma unroll 1
    for (int mt = 0; mt < 5; ++mt) {
        float acc[8][4];
        #pragma unroll
        for (int nt = 0; nt < 8; ++nt) {
            acc[nt][0] = acc[nt][1] = acc[nt][2] = acc[nt][3] = 0.0f;
        }
        uint32_t ah[2][4], al[2][4];
        const uint32_t rowoff = (uint32_t)((mt * 16 + (lane & 15)) * ASTR + (lane >> 4) * 16);
        #pragma unroll
        for (int ks = 0; ks < 2; ++ks) {
            ldmat4(ah[ks], aHiB + rowoff + ks * 32);
            ldmat4(al[ks], aLoB + rowoff + ks * 32);
        }
        #pragma unroll
        for (int ks = 0; ks < 2; ++ks) {
            #pragma unroll
            for (int nt = 0; nt < 8; ++nt) {
                mma16816(acc[nt], ah[ks], Bh[nt][ks]);
                mma16816(acc[nt], ah[ks], Bl[nt][ks]);
                mma16816(acc[nt], al[ks], Bh[nt][ks]);
            }
        }
        // epilogue: monotone-key atomicMax into per-voxel buf
        const int row0 = mt * 16 + g;
        const int row1 = row0 + 8;
        const int vi0 = row0 / PP, vi1 = row1 / PP;
        const int sv0 = warp * VPW + vi0, sv1 = warp * VPW + vi1;
        #pragma unroll
        for (int nt = 0; nt < 8; ++nt) {
            const int o = nt * 8 + 2 * t4;
            const uint32_t k0 = fkey(acc[nt][0]);
            const uint32_t k1 = fkey(acc[nt][1]);
            const uint32_t k2 = fkey(acc[nt][2]);
            const uint32_t k3 = fkey(acc[nt][3]);
            if (vi0 == vi1) {
                atomicMax(&buf[sv0][o],     k0 > k2 ? k0 : k2);
                atomicMax(&buf[sv0][o + 1], k1 > k3 ? k1 : k3);
            } else {
                atomicMax(&buf[sv0][o],     k0);
                atomicMax(&buf[sv0][o + 1], k1);
                atomicMax(&buf[sv1][o],     k2);
                atomicMax(&buf[sv1][o + 1], k3);
            }
        }
    }
    __syncwarp();

    // ---- final: unkey, BN, relu, store (scale > 0 => max commutes with BN) ----
    #pragma unroll
    for (int i = 0; i < 8; ++i) {
        const int idx = lane + i * 32;        // 0..255
        const int vi = idx >> 6, o = idx & 63;
        const int vv = v0 + vi;
        if (vv < V) {
            const float f = funkey(buf[warp * VPW + vi][o]);
            out[(size_t)vv * 64 + o] = fmaxf(0.0f, fmaf(f, scls[o], shfs[o]));
        }
    }
}

extern "C" void kernel_launch(void* const* d_in, const int* in_sizes, int n_in,
                              void* d_out, int out_size) {
    const float4* feats4     = (const float4*)d_in[0];
    const int*    num_points = (const int*)   d_in[1];
    const float*  W          = (const float*) d_in[3];
    const float*  gamma_     = (const float*) d_in[4];
    const float*  beta_      = (const float*) d_in[5];
    const float*  rmean      = (const float*) d_in[6];
    const float*  rvar       = (const float*) d_in[7];
    float* out = (float*)d_out;

    const int V = in_sizes[1];
    const int vox_per_cta = WARPS * VPW;
    const int grid = (V + vox_per_cta - 1) / vox_per_cta;
    lef_mma_kernel<<<grid, THREADS>>>(feats4, num_points, W, gamma_, beta_,
                                      rmean, rvar, out, V);
}

// round 6
// speedup vs baseline: 2.2380x; 1.0634x over previous
#include <cuda_runtime.h>
#include <cuda_bf16.h>
#include <stdint.h>

#define PP 20
#define VPW 4          // voxels per warp
#define WARPS 2
#define THREADS 64
#define ROWS 80        // A rows per warp = 5 m16 tiles
#define ASTR 80        // bytes per A row (32 bf16 = 64B data + 16B pad)

__device__ __forceinline__ uint32_t smem_u32(const void* p) {
    uint32_t a;
    asm("{ .reg .u64 t; cvta.to.shared.u64 t, %1; cvt.u32.u64 %0, t; }" : "=r"(a) : "l"(p));
    return a;
}
__device__ __forceinline__ float sqrt_apx(float x) {
    float r; asm("sqrt.approx.f32 %0,%1;" : "=f"(r) : "f"(x)); return r;
}
__device__ __forceinline__ uint32_t pack_bf2(float x, float y) {
    __nv_bfloat162 t = __floats2bfloat162_rn(x, y);
    return *(uint32_t*)&t;
}
__device__ __forceinline__ uint32_t pack_res2(float x, float y, uint32_t hipack) {
    __nv_bfloat162 h = *(__nv_bfloat162*)&hipack;
    return pack_bf2(x - __bfloat162float(h.x), y - __bfloat162float(h.y));
}
__device__ __forceinline__ void ldmat4(uint32_t* r, uint32_t addr) {
    asm volatile("ldmatrix.sync.aligned.m8n8.x4.shared.b16 {%0,%1,%2,%3}, [%4];"
        : "=r"(r[0]), "=r"(r[1]), "=r"(r[2]), "=r"(r[3]) : "r"(addr));
}
__device__ __forceinline__ void mma16816(float* c, const uint32_t* a, const uint32_t* b) {
    asm volatile("mma.sync.aligned.m16n8k16.row.col.f32.bf16.bf16.f32 "
        "{%0,%1,%2,%3},{%4,%5,%6,%7},{%8,%9},{%0,%1,%2,%3};"
        : "+f"(c[0]), "+f"(c[1]), "+f"(c[2]), "+f"(c[3])
        : "r"(a[0]), "r"(a[1]), "r"(a[2]), "r"(a[3]), "r"(b[0]), "r"(b[1]));
}
// permuted W lookup: k<20 -> dist weight row 7+k ; 20..26 -> node row k-20 ; else 0
__device__ __forceinline__ float wval(const float* __restrict__ W, int k, int n) {
    if (k < 20) return W[(7 + k) * 64 + n];
    if (k < 27) return W[(k - 20) * 64 + n];
    return 0.0f;
}

__global__ void __launch_bounds__(THREADS) lef_mma2_kernel(
    const float4* __restrict__ feats4,
    const int*    __restrict__ num_points,
    const float*  __restrict__ W,
    const float*  __restrict__ gamma_,
    const float*  __restrict__ beta_,
    const float*  __restrict__ rmean,
    const float*  __restrict__ rvar,
    float* __restrict__ out,
    int V)
{
    __shared__ __align__(16) uint8_t Ahi[WARPS][ROWS * ASTR];
    __shared__ __align__(16) uint8_t Alo[WARPS][ROWS * ASTR];
    __shared__ float4 cs4s[WARPS * VPW][PP];
    __shared__ float  sqs [WARPS * VPW][PP];
    __shared__ float  meanv[WARPS * VPW][3];
    __shared__ int    npvs[WARPS * VPW];
    __shared__ __align__(8) float shfs[64];

    const int tid  = threadIdx.x;
    const int warp = tid >> 5;
    const int lane = tid & 31;
    const int t4 = lane & 3, g = lane >> 2;

    // BN shift table (scale is folded into B below)
    if (tid < 64) {
        const float s = gamma_[tid] * rsqrtf(rvar[tid] + 1e-3f);
        shfs[tid] = beta_[tid] - rmean[tid] * s;
    }

    // ---- stage features (coalesced LDG.128) ----
    const int v0 = (blockIdx.x * WARPS + warp) * VPW;
    for (int t = lane; t < VPW * PP; t += 32) {
        const int vi = t / PP, p = t - vi * PP;
        const int vv = v0 + vi;
        float4 f = make_float4(0.f, 0.f, 0.f, 0.f);
        if (vv < V) f = feats4[(size_t)v0 * PP + t];
        const int sv = warp * VPW + vi;
        cs4s[sv][p] = f;
        sqs[sv][p]  = f.x * f.x + f.y * f.y + f.z * f.z;
    }
    if (lane < VPW) {
        const int vv = v0 + lane;
        npvs[warp * VPW + lane] = (vv < V) ? num_points[vv] : 1;
    }
    __syncwarp();

    // ---- per-voxel means (unmasked sum / npts, as reference) ----
    if (lane < 12) {
        const int vi = lane / 3, d = lane - vi * 3;
        const int sv = warp * VPW + vi;
        const float* c = (const float*)&cs4s[sv][0];
        float s = 0.0f;
        #pragma unroll
        for (int p = 0; p < PP; ++p) s += c[p * 4 + d];
        meanv[sv][d] = s / (float)npvs[sv];
    }
    __syncwarp();

    // ---- assemble A rows (hi/lo bf16) in voxel-tiled layout ----
    // row r<64: voxel r>>4, point r&15 ; row 64+j: voxel j>>2, point 16+(j&3)
    const uint32_t aHiB = smem_u32(&Ahi[warp][0]);
    const uint32_t aLoB = smem_u32(&Alo[warp][0]);
    #pragma unroll
    for (int r = lane; r < ROWS; r += 32) {
        int vi, p;
        if (r < 64) { vi = r >> 4; p = r & 15; }
        else        { vi = (r - 64) >> 2; p = 16 + ((r - 64) & 3); }
        const int sv = warp * VPW + vi;
        const float4 a  = cs4s[sv][p];
        const float sqp = sqs[sv][p];
        const int   np  = npvs[sv];
        const float pm  = (p < np) ? 1.0f : 0.0f;
        const float m0 = meanv[sv][0], m1 = meanv[sv][1], m2 = meanv[sv][2];

        uint32_t hi[16], lo[16];
        #pragma unroll
        for (int jj = 0; jj < 10; ++jj) {
            const int q0 = 2 * jj, q1 = q0 + 1;
            const float4 b0 = cs4s[sv][q0], b1 = cs4s[sv][q1];
            float dot0 = a.x * b0.x; dot0 = fmaf(a.y, b0.y, dot0); dot0 = fmaf(a.z, b0.z, dot0);
            float dot1 = a.x * b1.x; dot1 = fmaf(a.y, b1.y, dot1); dot1 = fmaf(a.z, b1.z, dot1);
            const float d20 = (sqp + sqs[sv][q0]) - 2.0f * dot0;
            const float d21 = (sqp + sqs[sv][q1]) - 2.0f * dot1;
            const float e0 = (d20 > 0.0f && q0 < np) ? sqrt_apx(d20) : 0.0f;
            const float e1 = (d21 > 0.0f && q1 < np) ? sqrt_apx(d21) : 0.0f;
            hi[jj] = pack_bf2(e0, e1);
            lo[jj] = pack_res2(e0, e1, hi[jj]);
        }
        const float n0 = a.x * pm, n1 = a.y * pm, n2 = a.z * pm, n3 = a.w * pm;
        const float n4 = (a.x - m0) * pm, n5 = (a.y - m1) * pm, n6 = (a.z - m2) * pm;
        hi[10] = pack_bf2(n0, n1); lo[10] = pack_res2(n0, n1, hi[10]);
        hi[11] = pack_bf2(n2, n3); lo[11] = pack_res2(n2, n3, hi[11]);
        hi[12] = pack_bf2(n4, n5); lo[12] = pack_res2(n4, n5, hi[12]);
        hi[13] = pack_bf2(n6, 0.f); lo[13] = pack_res2(n6, 0.f, hi[13]);
        hi[14] = hi[15] = lo[14] = lo[15] = 0u;

        uint8_t* rowHi = &Ahi[warp][r * ASTR];
        uint8_t* rowLo = &Alo[warp][r * ASTR];
        const int rot = (lane >> 3) & 3;              // de-conflict STS banks
        #pragma unroll
        for (int jj = 0; jj < 4; ++jj) {
            const int j = (jj + rot) & 3;
            *(uint4*)(rowHi + j * 16) = make_uint4(hi[4*j], hi[4*j+1], hi[4*j+2], hi[4*j+3]);
            *(uint4*)(rowLo + j * 16) = make_uint4(lo[4*j], lo[4*j+1], lo[4*j+2], lo[4*j+3]);
        }
    }
    __syncthreads();   // A tiles (warp-local) + shfs (cross-warp) visible

    const int vsel = g >> 2;   // tile-4 voxel owned by acc4[.][0..1]; [2..3] -> vsel+2

    // ---- two 32-column halves ----
    #pragma unroll 1
    for (int h = 0; h < 2; ++h) {
        // B fragments (hi/lo), BN scale folded into W
        uint32_t Bh[4][2][2], Bl[4][2][2];
        #pragma unroll
        for (int nt = 0; nt < 4; ++nt) {
            const int nn = h * 32 + nt * 8 + g;
            const float s = gamma_[nn] * rsqrtf(rvar[nn] + 1e-3f);
            #pragma unroll
            for (int ks = 0; ks < 2; ++ks) {
                const int k0 = ks * 16 + 2 * t4;
                const float w00 = wval(W, k0,     nn) * s;
                const float w01 = wval(W, k0 + 1, nn) * s;
                const float w10 = wval(W, k0 + 8, nn) * s;
                const float w11 = wval(W, k0 + 9, nn) * s;
                Bh[nt][ks][0] = pack_bf2(w00, w01);
                Bh[nt][ks][1] = pack_bf2(w10, w11);
                Bl[nt][ks][0] = pack_res2(w00, w01, Bh[nt][ks][0]);
                Bl[nt][ks][1] = pack_res2(w10, w11, Bh[nt][ks][1]);
            }
        }

        // tile 4 first (leftover points p=16..19 of all 4 voxels), hold acc4
        float acc4[4][4];
        {
            uint32_t a4h[2][4], a4l[2][4];
            const uint32_t ro4 = (uint32_t)((64 + (lane & 15)) * ASTR + (lane >> 4) * 16);
            ldmat4(a4h[0], aHiB + ro4);      ldmat4(a4h[1], aHiB + ro4 + 32);
            ldmat4(a4l[0], aLoB + ro4);      ldmat4(a4l[1], aLoB + ro4 + 32);
            #pragma unroll
            for (int nt = 0; nt < 4; ++nt)
                acc4[nt][0] = acc4[nt][1] = acc4[nt][2] = acc4[nt][3] = 0.0f;
            #pragma unroll
            for (int ks = 0; ks < 2; ++ks)
                #pragma unroll
                for (int nt = 0; nt < 4; ++nt) {
                    mma16816(acc4[nt], a4h[ks], Bh[nt][ks]);
                    mma16816(acc4[nt], a4h[ks], Bl[nt][ks]);
                    mma16816(acc4[nt], a4l[ks], Bh[nt][ks]);
                }
        }

        // per-voxel tiles + register/shuffle max epilogue
        #pragma unroll
        for (int vi = 0; vi < VPW; ++vi) {
            uint32_t ah[2][4], al[2][4];
            const uint32_t ro = (uint32_t)((vi * 16 + (lane & 15)) * ASTR + (lane >> 4) * 16);
            ldmat4(ah[0], aHiB + ro);      ldmat4(ah[1], aHiB + ro + 32);
            ldmat4(al[0], aLoB + ro);      ldmat4(al[1], aLoB + ro + 32);
            float acc[4][4];
            #pragma unroll
            for (int nt = 0; nt < 4; ++nt)
                acc[nt][0] = acc[nt][1] = acc[nt][2] = acc[nt][3] = 0.0f;
            #pragma unroll
            for (int ks = 0; ks < 2; ++ks)
                #pragma unroll
                for (int nt = 0; nt < 4; ++nt) {
                    mma16816(acc[nt], ah[ks], Bh[nt][ks]);
                    mma16816(acc[nt], ah[ks], Bl[nt][ks]);
                    mma16816(acc[nt], al[ks], Bh[nt][ks]);
                }

            // per-lane max over this voxel's rows (p 0..15), merge tile-4 rows
            float pmx[8];
            #pragma unroll
            for (int nt = 0; nt < 4; ++nt) {
                pmx[2*nt]   = fmaxf(acc[nt][0], acc[nt][2]);
                pmx[2*nt+1] = fmaxf(acc[nt][1], acc[nt][3]);
            }
            if (vsel == vi) {
                #pragma unroll
                for (int nt = 0; nt < 4; ++nt) {
                    pmx[2*nt]   = fmaxf(pmx[2*nt],   acc4[nt][0]);
                    pmx[2*nt+1] = fmaxf(pmx[2*nt+1], acc4[nt][1]);
                }
            }
            if (vsel == vi - 2) {
                #pragma unroll
                for (int nt = 0; nt < 4; ++nt) {
                    pmx[2*nt]   = fmaxf(pmx[2*nt],   acc4[nt][2]);
                    pmx[2*nt+1] = fmaxf(pmx[2*nt+1], acc4[nt][3]);
                }
            }
            // butterfly max over the 8 g-lanes (lane bits 2..4)
            #pragma unroll
            for (int off = 4; off <= 16; off <<= 1)
                #pragma unroll
                for (int i = 0; i < 8; ++i)
                    pmx[i] = fmaxf(pmx[i], __shfl_xor_sync(0xffffffffu, pmx[i], off));

            // lanes g<4 store cols h*32 + g*8 + 2*t4 (+1): 32 cols, coalesced
            const int vv = v0 + vi;
            if (g < 4 && vv < V) {
                const float va = (g & 2) ? ((g & 1) ? pmx[6] : pmx[4])
                                         : ((g & 1) ? pmx[2] : pmx[0]);
                const float vb = (g & 2) ? ((g & 1) ? pmx[7] : pmx[5])
                                         : ((g & 1) ? pmx[3] : pmx[1]);
                const int col = h * 32 + g * 8 + 2 * t4;
                const float2 sh = *(const float2*)&shfs[col];
                float2 r2;
                r2.x = fmaxf(0.0f, va + sh.x);
                r2.y = fmaxf(0.0f, vb + sh.y);
                *(float2*)&out[(size_t)vv * 64 + col] = r2;
            }
        }
    }
}

extern "C" void kernel_launch(void* const* d_in, const int* in_sizes, int n_in,
                              void* d_out, int out_size) {
    const float4* feats4     = (const float4*)d_in[0];
    const int*    num_points = (const int*)   d_in[1];
    const float*  W          = (const float*) d_in[3];
    const float*  gamma_     = (const float*) d_in[4];
    const float*  beta_      = (const float*) d_in[5];
    const float*  rmean      = (const float*) d_in[6];
    const float*  rvar       = (const float*) d_in[7];
    float* out = (float*)d_out;

    const int V = in_sizes[1];
    const int vox_per_cta = WARPS * VPW;
    const int grid = (V + vox_per_cta - 1) / vox_per_cta;
    lef_mma2_kernel<<<grid, THREADS>>>(feats4, num_points, W, gamma_, beta_,
                                       rmean, rvar, out, V);
}

// round 7
// speedup vs baseline: 2.2743x; 1.0162x over previous
#include <cuda_runtime.h>
#include <cuda_bf16.h>
#include <stdint.h>

#define PP 20
#define VPW 4          // voxels per warp
#define WARPS 2
#define THREADS 64
#define ROWS 80        // A rows per warp = 5 m16 tiles
#define ASTR 80        // bytes per A row (32 bf16 = 64B data + 16B pad, conflict-free banks)

// precomputed by lef_prep: B fragments (BN-scale folded, permuted, bf16 hi/lo)
// layout: [h(2)][lane(32)][ 16 x hi | 16 x lo ]  (hi idx = (nt*2+ks)*2+pair)
__device__ uint32_t g_Btab[2 * 32 * 32];
__device__ float    g_shift[64];

__device__ __forceinline__ uint32_t smem_u32(const void* p) {
    uint32_t a;
    asm("{ .reg .u64 t; cvta.to.shared.u64 t, %1; cvt.u32.u64 %0, t; }" : "=r"(a) : "l"(p));
    return a;
}
__device__ __forceinline__ float sqrt_apx(float x) {
    float r; asm("sqrt.approx.f32 %0,%1;" : "=f"(r) : "f"(x)); return r;
}
__device__ __forceinline__ uint32_t pack_bf2(float x, float y) {
    __nv_bfloat162 t = __floats2bfloat162_rn(x, y);
    return *(uint32_t*)&t;
}
__device__ __forceinline__ uint32_t pack_res2(float x, float y, uint32_t hipack) {
    __nv_bfloat162 h = *(__nv_bfloat162*)&hipack;
    return pack_bf2(x - __bfloat162float(h.x), y - __bfloat162float(h.y));
}
__device__ __forceinline__ void ldmat4(uint32_t* r, uint32_t addr) {
    asm volatile("ldmatrix.sync.aligned.m8n8.x4.shared.b16 {%0,%1,%2,%3}, [%4];"
        : "=r"(r[0]), "=r"(r[1]), "=r"(r[2]), "=r"(r[3]) : "r"(addr));
}
__device__ __forceinline__ void mma16816(float* c, const uint32_t* a, const uint32_t* b) {
    asm volatile("mma.sync.aligned.m16n8k16.row.col.f32.bf16.bf16.f32 "
        "{%0,%1,%2,%3},{%4,%5,%6,%7},{%8,%9},{%0,%1,%2,%3};"
        : "+f"(c[0]), "+f"(c[1]), "+f"(c[2]), "+f"(c[3])
        : "r"(a[0]), "r"(a[1]), "r"(a[2]), "r"(a[3]), "r"(b[0]), "r"(b[1]));
}
// permuted W lookup: k<20 -> dist weight row 7+k ; 20..26 -> node row k-20 ; else 0
__device__ __forceinline__ float wval(const float* __restrict__ W, int k, int n) {
    if (k < 20) return W[(7 + k) * 64 + n];
    if (k < 27) return W[(k - 20) * 64 + n];
    return 0.0f;
}

// ---- pre-kernel: build B fragment table + shift table (once) ----
__global__ void lef_prep(const float* __restrict__ W, const float* __restrict__ gamma_,
                         const float* __restrict__ beta_, const float* __restrict__ rmean,
                         const float* __restrict__ rvar)
{
    const int t = threadIdx.x;                    // 64 threads
    {
        const float s = gamma_[t] * rsqrtf(rvar[t] + 1e-3f);
        g_shift[t] = beta_[t] - rmean[t] * s;
    }
    const int h = t >> 5, lane = t & 31, t4 = lane & 3, gg = lane >> 2;
    uint32_t vals[32];
    #pragma unroll
    for (int nt = 0; nt < 4; ++nt) {
        const int nn = h * 32 + nt * 8 + gg;
        const float s = gamma_[nn] * rsqrtf(rvar[nn] + 1e-3f);
        #pragma unroll
        for (int ks = 0; ks < 2; ++ks) {
            const int k0 = ks * 16 + 2 * t4;
            const float w00 = wval(W, k0,     nn) * s;
            const float w01 = wval(W, k0 + 1, nn) * s;
            const float w10 = wval(W, k0 + 8, nn) * s;
            const float w11 = wval(W, k0 + 9, nn) * s;
            const uint32_t h0 = pack_bf2(w00, w01);
            const uint32_t h1 = pack_bf2(w10, w11);
            vals[(nt * 2 + ks) * 2 + 0] = h0;
            vals[(nt * 2 + ks) * 2 + 1] = h1;
            vals[16 + (nt * 2 + ks) * 2 + 0] = pack_res2(w00, w01, h0);
            vals[16 + (nt * 2 + ks) * 2 + 1] = pack_res2(w10, w11, h1);
        }
    }
    uint32_t* dst = &g_Btab[(h * 32 + lane) * 32];
    #pragma unroll
    for (int i = 0; i < 32; ++i) dst[i] = vals[i];
}

__global__ void __launch_bounds__(THREADS) lef_mma3_kernel(
    const float4* __restrict__ feats4,
    const int*    __restrict__ num_points,
    float* __restrict__ out,
    int V)
{
    __shared__ __align__(16) uint8_t Ahi[WARPS][ROWS * ASTR];
    __shared__ __align__(16) uint8_t Alo[WARPS][ROWS * ASTR];
    __shared__ float4 cs4s[WARPS * VPW][PP];
    __shared__ float  sqs [WARPS * VPW][PP];
    __shared__ float  meanv[WARPS * VPW][3];
    __shared__ int    npvs[WARPS * VPW];
    __shared__ __align__(8) float shfs[64];

    const int tid  = threadIdx.x;
    const int warp = tid >> 5;
    const int lane = tid & 31;
    const int t4 = lane & 3, g = lane >> 2;

    if (tid < 64) shfs[tid] = g_shift[tid];

    // ---- stage features (coalesced LDG.128) ----
    const int v0 = (blockIdx.x * WARPS + warp) * VPW;
    for (int t = lane; t < VPW * PP; t += 32) {
        const int vi = t / PP, p = t - vi * PP;
        const int vv = v0 + vi;
        float4 f = make_float4(0.f, 0.f, 0.f, 0.f);
        if (vv < V) f = feats4[(size_t)v0 * PP + t];
        const int sv = warp * VPW + vi;
        cs4s[sv][p] = f;
        sqs[sv][p]  = f.x * f.x + f.y * f.y + f.z * f.z;
    }
    if (lane < VPW) {
        const int vv = v0 + lane;
        npvs[warp * VPW + lane] = (vv < V) ? num_points[vv] : 1;
    }
    __syncwarp();

    // ---- per-voxel means (unmasked sum / npts, as reference) ----
    if (lane < 12) {
        const int vi = lane / 3, d = lane - vi * 3;
        const int sv = warp * VPW + vi;
        const float* c = (const float*)&cs4s[sv][0];
        float s = 0.0f;
        #pragma unroll
        for (int p = 0; p < PP; ++p) s += c[p * 4 + d];
        meanv[sv][d] = s / (float)npvs[sv];
    }
    __syncwarp();

    // ---- assemble A rows (hi/lo bf16) in voxel-tiled layout ----
    // row r<64: voxel r>>4, point r&15 ; row 64+j: voxel j>>2, point 16+(j&3)
    const uint32_t aHiB = smem_u32(&Ahi[warp][0]);
    const uint32_t aLoB = smem_u32(&Alo[warp][0]);
    #pragma unroll
    for (int r = lane; r < ROWS; r += 32) {
        int vi, p;
        if (r < 64) { vi = r >> 4; p = r & 15; }
        else        { vi = (r - 64) >> 2; p = 16 + ((r - 64) & 3); }
        const int sv = warp * VPW + vi;
        const float4 a  = cs4s[sv][p];
        const float sqp = sqs[sv][p];
        const int   np  = npvs[sv];
        const float pm  = (p < np) ? 1.0f : 0.0f;
        const float m0 = meanv[sv][0], m1 = meanv[sv][1], m2 = meanv[sv][2];

        uint32_t hi[16], lo[16];
        #pragma unroll
        for (int jj = 0; jj < 10; ++jj) {
            const int q0 = 2 * jj, q1 = q0 + 1;
            const float4 b0 = cs4s[sv][q0], b1 = cs4s[sv][q1];
            float dot0 = a.x * b0.x; dot0 = fmaf(a.y, b0.y, dot0); dot0 = fmaf(a.z, b0.z, dot0);
            float dot1 = a.x * b1.x; dot1 = fmaf(a.y, b1.y, dot1); dot1 = fmaf(a.z, b1.z, dot1);
            const float d20 = (sqp + sqs[sv][q0]) - 2.0f * dot0;
            const float d21 = (sqp + sqs[sv][q1]) - 2.0f * dot1;
            const float e0 = (d20 > 0.0f && q0 < np) ? sqrt_apx(d20) : 0.0f;
            const float e1 = (d21 > 0.0f && q1 < np) ? sqrt_apx(d21) : 0.0f;
            hi[jj] = pack_bf2(e0, e1);
            lo[jj] = pack_res2(e0, e1, hi[jj]);
        }
        const float n0 = a.x * pm, n1 = a.y * pm, n2 = a.z * pm, n3 = a.w * pm;
        const float n4 = (a.x - m0) * pm, n5 = (a.y - m1) * pm, n6 = (a.z - m2) * pm;
        hi[10] = pack_bf2(n0, n1); lo[10] = pack_res2(n0, n1, hi[10]);
        hi[11] = pack_bf2(n2, n3); lo[11] = pack_res2(n2, n3, hi[11]);
        hi[12] = pack_bf2(n4, n5); lo[12] = pack_res2(n4, n5, hi[12]);
        hi[13] = pack_bf2(n6, 0.f); lo[13] = pack_res2(n6, 0.f, hi[13]);
        hi[14] = hi[15] = lo[14] = lo[15] = 0u;

        uint8_t* rowHi = &Ahi[warp][r * ASTR];
        uint8_t* rowLo = &Alo[warp][r * ASTR];
        const int rot = (lane >> 3) & 3;              // de-conflict STS banks
        #pragma unroll
        for (int jj = 0; jj < 4; ++jj) {
            const int j = (jj + rot) & 3;
            *(uint4*)(rowHi + j * 16) = make_uint4(hi[4*j], hi[4*j+1], hi[4*j+2], hi[4*j+3]);
            *(uint4*)(rowLo + j * 16) = make_uint4(lo[4*j], lo[4*j+1], lo[4*j+2], lo[4*j+3]);
        }
    }
    __syncthreads();   // A tiles + shfs visible

    const int vsel = g >> 2;   // tile-4 voxel owned by acc4[.][0..1]; [2..3] -> vsel+2

    // ---- two 32-column halves ----
    #pragma unroll 1
    for (int h = 0; h < 2; ++h) {
        // B fragments: straight LDG.128 from precomputed table
        uint32_t BH[16], BL[16];
        {
            const uint4* bt = (const uint4*)&g_Btab[(h * 32 + lane) * 32];
            #pragma unroll
            for (int i = 0; i < 4; ++i) {
                const uint4 q = bt[i];
                BH[4*i] = q.x; BH[4*i+1] = q.y; BH[4*i+2] = q.z; BH[4*i+3] = q.w;
            }
            #pragma unroll
            for (int i = 0; i < 4; ++i) {
                const uint4 q = bt[4 + i];
                BL[4*i] = q.x; BL[4*i+1] = q.y; BL[4*i+2] = q.z; BL[4*i+3] = q.w;
            }
        }
        #define BHF(nt, ks) (&BH[((nt) * 2 + (ks)) * 2])
        #define BLF(nt, ks) (&BL[((nt) * 2 + (ks)) * 2])

        // tile 4 first (leftover points p=16..19 of all 4 voxels), hold acc4
        float acc4[4][4];
        {
            uint32_t a4h[2][4], a4l[2][4];
            const uint32_t ro4 = (uint32_t)((64 + (lane & 15)) * ASTR + (lane >> 4) * 16);
            ldmat4(a4h[0], aHiB + ro4);      ldmat4(a4h[1], aHiB + ro4 + 32);
            ldmat4(a4l[0], aLoB + ro4);      ldmat4(a4l[1], aLoB + ro4 + 32);
            #pragma unroll
            for (int nt = 0; nt < 4; ++nt)
                acc4[nt][0] = acc4[nt][1] = acc4[nt][2] = acc4[nt][3] = 0.0f;
            #pragma unroll
            for (int ks = 0; ks < 2; ++ks)
                #pragma unroll
                for (int nt = 0; nt < 4; ++nt) {
                    mma16816(acc4[nt], a4h[ks], BHF(nt, ks));
                    mma16816(acc4[nt], a4h[ks], BLF(nt, ks));
                    mma16816(acc4[nt], a4l[ks], BHF(nt, ks));
                }
        }

        // per-voxel tiles + lean shuffle-max epilogue
        #pragma unroll
        for (int vi = 0; vi < VPW; ++vi) {
            uint32_t ah[2][4], al[2][4];
            const uint32_t ro = (uint32_t)((vi * 16 + (lane & 15)) * ASTR + (lane >> 4) * 16);
            ldmat4(ah[0], aHiB + ro);      ldmat4(ah[1], aHiB + ro + 32);
            ldmat4(al[0], aLoB + ro);      ldmat4(al[1], aLoB + ro + 32);
            float acc[4][4];
            #pragma unroll
            for (int nt = 0; nt < 4; ++nt)
                acc[nt][0] = acc[nt][1] = acc[nt][2] = acc[nt][3] = 0.0f;
            #pragma unroll
            for (int ks = 0; ks < 2; ++ks)
                #pragma unroll
                for (int nt = 0; nt < 4; ++nt) {
                    mma16816(acc[nt], ah[ks], BHF(nt, ks));
                    mma16816(acc[nt], ah[ks], BLF(nt, ks));
                    mma16816(acc[nt], al[ks], BHF(nt, ks));
                }

            // per-lane max over this voxel's rows (p 0..15), merge tile-4 rows
            float pmx[8];
            #pragma unroll
            for (int nt = 0; nt < 4; ++nt) {
                pmx[2*nt]   = fmaxf(acc[nt][0], acc[nt][2]);
                pmx[2*nt+1] = fmaxf(acc[nt][1], acc[nt][3]);
            }
            if (vsel == vi) {
                #pragma unroll
                for (int nt = 0; nt < 4; ++nt) {
                    pmx[2*nt]   = fmaxf(pmx[2*nt],   acc4[nt][0]);
                    pmx[2*nt+1] = fmaxf(pmx[2*nt+1], acc4[nt][1]);
                }
            }
            if (vsel == vi - 2) {
                #pragma unroll
                for (int nt = 0; nt < 4; ++nt) {
                    pmx[2*nt]   = fmaxf(pmx[2*nt],   acc4[nt][2]);
                    pmx[2*nt+1] = fmaxf(pmx[2*nt+1], acc4[nt][3]);
                }
            }

            // lean butterfly: drop half the values each round
            const bool b4 = (lane & 16) != 0;
            float q[4];
            #pragma unroll
            for (int i = 0; i < 4; ++i) {
                const float send = b4 ? pmx[i] : pmx[4 + i];
                const float recv = __shfl_xor_sync(0xffffffffu, send, 16);
                q[i] = fmaxf(b4 ? pmx[4 + i] : pmx[i], recv);
            }
            const bool b3 = (lane & 8) != 0;
            float r2v[2];
            #pragma unroll
            for (int i = 0; i < 2; ++i) {
                const float send = b3 ? q[i] : q[2 + i];
                const float recv = __shfl_xor_sync(0xffffffffu, send, 8);
                r2v[i] = fmaxf(b3 ? q[2 + i] : q[i], recv);
            }
            const float f0 = fmaxf(r2v[0], __shfl_xor_sync(0xffffffffu, r2v[0], 4));
            const float f1 = fmaxf(r2v[1], __shfl_xor_sync(0xffffffffu, r2v[1], 4));

            // lanes with bit2==0 store cols ntp*8 + 2*t4 (+1)
            const int vv = v0 + vi;
            if ((lane & 4) == 0 && vv < V) {
                const int ntp = (((lane >> 4) & 1) << 1) | ((lane >> 3) & 1);
                const int col = h * 32 + ntp * 8 + 2 * t4;
                const float2 sh = *(const float2*)&shfs[col];
                float2 r2;
                r2.x = fmaxf(0.0f, f0 + sh.x);
                r2.y = fmaxf(0.0f, f1 + sh.y);
                *(float2*)&out[(size_t)vv * 64 + col] = r2;
            }
        }
        #undef BHF
        #undef BLF
    }
}

extern "C" void kernel_launch(void* const* d_in, const int* in_sizes, int n_in,
                              void* d_out, int out_size) {
    const float4* feats4     = (const float4*)d_in[0];
    const int*    num_points = (const int*)   d_in[1];
    const float*  W          = (const float*) d_in[3];
    const float*  gamma_     = (const float*) d_in[4];
    const float*  beta_      = (const float*) d_in[5];
    const float*  rmean      = (const float*) d_in[6];
    const float*  rvar       = (const float*) d_in[7];
    float* out = (float*)d_out;

    const int V = in_sizes[1];
    lef_prep<<<1, 64>>>(W, gamma_, beta_, rmean, rvar);
    const int vox_per_cta = WARPS * VPW;
    const int grid = (V + vox_per_cta - 1) / vox_per_cta;
    lef_mma3_kernel<<<grid, THREADS>>>(feats4, num_points, out, V);
}